// round 16
// baseline (speedup 1.0000x reference)
#include <cuda_runtime.h>
#include <cuda_fp16.h>
#include <math.h>
#include <stdint.h>

// ---------------- problem constants ----------------
#define DM    1024
#define DI    2048
#define LSEQ  4096
#define BATCH 2
#define ROWS  (BATCH*LSEQ)    // 8192
#define XPJ   68
#define DTR   64
#define NCH   32
#define CL    (LSEQ/NCH)      // 128

// ---------------- fp32 scratch ----------------
__device__ float g_xdbl[(size_t)ROWS*XPJ];
__device__ float g_h   [(size_t)ROWS*DM];
__device__ float g_part[4][(size_t)ROWS*XPJ];
// chunked-scan state
__device__ float g_ch0[BATCH*NCH*DI];
__device__ float g_ch1[BATCH*NCH*DI];
__device__ float g_chS[BATCH*NCH*DI];
__device__ float g_hs0[BATCH*NCH*DI];
__device__ float g_hs1[BATCH*NCH*DI];
// ---------------- fp16 scratch ----------------
__device__ __half g_xzh  [(size_t)ROWS*2*DI];
__device__ __half g_dth  [(size_t)ROWS*DI];
__device__ __half g_ln1h [(size_t)ROWS*DM];
__device__ __half g_xph  [(size_t)ROWS*DI];
__device__ __half g_xdblh[(size_t)ROWS*DTR];
__device__ __half g_gateh[(size_t)ROWS*DI];
__device__ __half g_ln2h [(size_t)ROWS*DM];
__device__ __half g_f1h  [(size_t)ROWS*DM];
// fp16 weights
__device__ __half g_w_inh  [(size_t)2*DI*DM];
__device__ __half g_w_xprjh[(size_t)XPJ*DI];
__device__ __half g_w_dth  [(size_t)DI*DTR];
__device__ __half g_w_outh [(size_t)DM*DI];
__device__ __half g_ffn1h  [(size_t)DM*DM];
__device__ __half g_ffn2h  [(size_t)DM*DM];

// ==================== helpers ====================
__device__ __forceinline__ uint32_t smem_u32(const void* p) {
    uint32_t a;
    asm("{ .reg .u64 t; cvta.to.shared.u64 t, %1; cvt.u32.u64 %0, t; }" : "=r"(a) : "l"(p));
    return a;
}
__device__ __forceinline__ void cp16(uint32_t sm, const void* g) {
    asm volatile("cp.async.cg.shared.global [%0], [%1], 16;" :: "r"(sm), "l"(g));
}
__device__ __forceinline__ void cp16z(uint32_t sm, const void* g, uint32_t valid) {
    uint32_t sz = valid ? 16u : 0u;
    asm volatile("cp.async.cg.shared.global [%0], [%1], 16, %2;" :: "r"(sm), "l"(g), "r"(sz));
}
#define CP_COMMIT() asm volatile("cp.async.commit_group;" ::: "memory")
#define CP_WAIT2()  asm volatile("cp.async.wait_group 2;" ::: "memory")

__device__ __forceinline__ void mma16(float* c, const uint32_t* a, const uint32_t* b) {
    asm volatile("mma.sync.aligned.m16n8k16.row.col.f32.f16.f16.f32 "
                 "{%0,%1,%2,%3}, {%4,%5,%6,%7}, {%8,%9}, {%0,%1,%2,%3};"
                 : "+f"(c[0]), "+f"(c[1]), "+f"(c[2]), "+f"(c[3])
                 : "r"(a[0]), "r"(a[1]), "r"(a[2]), "r"(a[3]),
                   "r"(b[0]), "r"(b[1]));
}
#define LDSM4(r0, r1, r2, r3, addr) \
    asm volatile("ldmatrix.sync.aligned.m8n8.x4.shared.b16 {%0,%1,%2,%3}, [%4];" \
                 : "=r"(r0), "=r"(r1), "=r"(r2), "=r"(r3) : "r"(addr))

// ==================== fp16 mma.sync GEMM ====================
enum { EPI_NONE = 0, EPI_SP_BIAS = 1, EPI_RELU_BIAS = 2, EPI_RES = 3, EPI_BIAS_RES = 4 };

#define KTILE       64
#define TILE_BYTES  16384
#define STAGE_BYTES (2 * TILE_BYTES)
#define HGEMM_SMEM  (3 * STAGE_BYTES)         // 98304 -> 2 CTAs/SM

template<int EPI, bool HOUT>
__global__ __launch_bounds__(256, 2)
void hgemm_kernel(const __half* __restrict__ A, int lda,
                  const __half* __restrict__ W, int ldw,
                  const float* __restrict__ bias,
                  const float* __restrict__ res,
                  float* __restrict__ Cf,
                  __half* __restrict__ Ch,
                  int N, int K, int ldc,
                  int nbx, int kStride, size_t outStride)
{
    extern __shared__ char smraw[];
    const uint32_t sb = smem_u32(smraw);
    const int tid  = threadIdx.x;
    const int wid  = tid >> 5;
    const int lane = tid & 31;
    const int grp  = lane >> 2;
    const int thr  = lane & 3;
    const int bx   = blockIdx.x;
    const int sp   = bx / nbx;
    const int m0 = blockIdx.y * 128;
    const int n0 = (bx % nbx) * 128;
    A  += (size_t)sp * kStride;
    W  += (size_t)sp * kStride;
    Cf += (size_t)sp * outStride;
    const int KT = K / KTILE;
    const int wM = (wid & 3) * 32;
    const int wN = (wid >> 2) * 64;

    auto load_tile = [&](int kt) {
        const uint32_t st = sb + (kt % 3) * STAGE_BYTES;
        const int k0 = kt * KTILE;
        #pragma unroll
        for (int i = 0; i < 4; i++) {
            const int idx = tid + 256 * i;
            const int row = idx >> 3;
            const int c   = idx & 7;
            const uint32_t soff = (uint32_t)(row * 128 + ((c ^ (row & 7)) << 4));
            cp16(st + soff, A + (size_t)(m0 + row) * lda + k0 + c * 8);
            const int nr = n0 + row;
            const uint32_t valid = (nr < N);
            cp16z(st + TILE_BYTES + soff,
                  W + (size_t)(valid ? nr : 0) * ldw + k0 + c * 8, valid);
        }
    };

    float acc[2][8][4];
    #pragma unroll
    for (int mt = 0; mt < 2; mt++)
        #pragma unroll
        for (int nt = 0; nt < 8; nt++)
            #pragma unroll
            for (int q = 0; q < 4; q++) acc[mt][nt][q] = 0.f;

    uint32_t aOff[2]; int a7[2];
    #pragma unroll
    for (int mt = 0; mt < 2; mt++) {
        const int r = wM + mt * 16 + ((lane >> 3) & 1) * 8 + (lane & 7);
        aOff[mt] = (uint32_t)(r * 128); a7[mt] = r & 7;
    }
    const int aHi = lane >> 4;
    uint32_t bOff[4]; int b7[4];
    #pragma unroll
    for (int j = 0; j < 4; j++) {
        const int r = wN + j * 16 + (lane >> 4) * 8 + (lane & 7);
        bOff[j] = (uint32_t)(r * 128); b7[j] = r & 7;
    }
    const int bHi = (lane >> 3) & 1;

    load_tile(0); CP_COMMIT();
    if (KT > 1) load_tile(1);
    CP_COMMIT();

    for (int kt = 0; kt < KT; kt++) {
        if (kt + 2 < KT) load_tile(kt + 2);
        CP_COMMIT();
        CP_WAIT2();
        __syncthreads();

        const uint32_t Ab = sb + (kt % 3) * STAGE_BYTES;
        const uint32_t Bb = Ab + TILE_BYTES;
        #pragma unroll
        for (int ks = 0; ks < 4; ks++) {
            uint32_t af[2][4];
            #pragma unroll
            for (int mt = 0; mt < 2; mt++) {
                const uint32_t ad = Ab + aOff[mt]
                    + (uint32_t)((((ks << 1) + aHi) ^ a7[mt]) << 4);
                LDSM4(af[mt][0], af[mt][1], af[mt][2], af[mt][3], ad);
            }
            uint32_t bf[8][2];
            #pragma unroll
            for (int j = 0; j < 4; j++) {
                const uint32_t bd = Bb + bOff[j]
                    + (uint32_t)((((ks << 1) + bHi) ^ b7[j]) << 4);
                uint32_t r0, r1, r2, r3;
                LDSM4(r0, r1, r2, r3, bd);
                bf[2*j][0] = r0; bf[2*j][1] = r1;
                bf[2*j+1][0] = r2; bf[2*j+1][1] = r3;
            }
            #pragma unroll
            for (int mt = 0; mt < 2; mt++)
                #pragma unroll
                for (int nt = 0; nt < 8; nt++)
                    mma16(acc[mt][nt], af[mt], bf[nt]);
        }
        __syncthreads();
    }

    // epilogue
    #pragma unroll
    for (int mt = 0; mt < 2; mt++) {
        const int mA = m0 + wM + mt * 16 + grp;
        #pragma unroll
        for (int nt = 0; nt < 8; nt++) {
            const int col = n0 + wN + nt * 8 + 2 * thr;
            if (col >= N) continue;
            float v0 = acc[mt][nt][0], v1 = acc[mt][nt][1];
            float v2 = acc[mt][nt][2], v3 = acc[mt][nt][3];
            if (EPI == EPI_SP_BIAS) {
                const float b0 = bias[col], b1 = bias[col + 1];
                v0 += b0; v1 += b1; v2 += b0; v3 += b1;
                v0 = (v0 > 20.f) ? v0 : log1pf(expf(v0));
                v1 = (v1 > 20.f) ? v1 : log1pf(expf(v1));
                v2 = (v2 > 20.f) ? v2 : log1pf(expf(v2));
                v3 = (v3 > 20.f) ? v3 : log1pf(expf(v3));
            } else if (EPI == EPI_RELU_BIAS) {
                const float b0 = bias[col], b1 = bias[col + 1];
                v0 = fmaxf(v0 + b0, 0.f); v1 = fmaxf(v1 + b1, 0.f);
                v2 = fmaxf(v2 + b0, 0.f); v3 = fmaxf(v3 + b1, 0.f);
            } else if (EPI == EPI_RES) {
                const float2 r0 = *(const float2*)(res + (size_t)mA * ldc + col);
                const float2 r1 = *(const float2*)(res + (size_t)(mA + 8) * ldc + col);
                v0 += r0.x; v1 += r0.y; v2 += r1.x; v3 += r1.y;
            } else if (EPI == EPI_BIAS_RES) {
                const float b0 = bias[col], b1 = bias[col + 1];
                const float2 r0 = *(const float2*)(res + (size_t)mA * ldc + col);
                const float2 r1 = *(const float2*)(res + (size_t)(mA + 8) * ldc + col);
                v0 += b0 + r0.x; v1 += b1 + r0.y; v2 += b0 + r1.x; v3 += b1 + r1.y;
            }
            if (HOUT) {
                *(__half2*)(Ch + (size_t)mA * ldc + col)       = __floats2half2_rn(v0, v1);
                *(__half2*)(Ch + (size_t)(mA + 8) * ldc + col) = __floats2half2_rn(v2, v3);
            } else {
                *(float2*)(Cf + (size_t)mA * ldc + col)       = make_float2(v0, v1);
                *(float2*)(Cf + (size_t)(mA + 8) * ldc + col) = make_float2(v2, v3);
            }
        }
    }
}

// ---------------- weight fp32 -> fp16 ----------------
__global__ void cvt_weights(const float4* s0, int n0, const float4* s1, int n1,
                            const float4* s2, int n2, const float4* s3, int n3,
                            const float4* s4, int n4, const float4* s5, int n5)
{
    int i = blockIdx.x * 256 + threadIdx.x;
    const float4* s; __half2* d;
    __half2* d0 = (__half2*)g_w_inh;  __half2* d1 = (__half2*)g_w_xprjh;
    __half2* d2 = (__half2*)g_w_dth;  __half2* d3 = (__half2*)g_w_outh;
    __half2* d4 = (__half2*)g_ffn1h;  __half2* d5 = (__half2*)g_ffn2h;
    if      (i < n0) { s = s0; d = d0; }
    else if ((i -= n0) < n1) { s = s1; d = d1; }
    else if ((i -= n1) < n2) { s = s2; d = d2; }
    else if ((i -= n2) < n3) { s = s3; d = d3; }
    else if ((i -= n3) < n4) { s = s4; d = d4; }
    else if ((i -= n4) < n5) { s = s5; d = d5; }
    else return;
    const float4 v = s[i];
    d[2*i]   = __floats2half2_rn(v.x, v.y);
    d[2*i+1] = __floats2half2_rn(v.z, v.w);
}

// ---------------- split-K reduce for x-proj ----------------
__global__ void xproj_reduce()
{
    const int i = blockIdx.x * 256 + threadIdx.x;
    if (i >= ROWS * XPJ) return;
    const float v = g_part[0][i] + g_part[1][i] + g_part[2][i] + g_part[3][i];
    g_xdbl[i] = v;
    const int m = i / XPJ, j = i - m * XPJ;
    if (j < DTR) g_xdblh[(size_t)m * DTR + j] = __float2half_rn(v);
}

// ---------------- LayerNorm -> fp16 out ----------------
__global__ void ln_kernel(const float* __restrict__ in,
                          const float* __restrict__ g,
                          const float* __restrict__ b,
                          __half* __restrict__ out)
{
    const int row = blockIdx.x;
    const int t = threadIdx.x;
    const float4* p = (const float4*)(in + (size_t)row * DM);
    float4 v = p[t];
    float s1 = v.x + v.y + v.z + v.w;
    float s2 = v.x*v.x + v.y*v.y + v.z*v.z + v.w*v.w;
    #pragma unroll
    for (int o = 16; o > 0; o >>= 1) {
        s1 += __shfl_xor_sync(0xFFFFFFFFu, s1, o);
        s2 += __shfl_xor_sync(0xFFFFFFFFu, s2, o);
    }
    __shared__ float sh1[8], sh2[8];
    if ((t & 31) == 0) { sh1[t >> 5] = s1; sh2[t >> 5] = s2; }
    __syncthreads();
    float t1 = 0.f, t2 = 0.f;
    #pragma unroll
    for (int i = 0; i < 8; i++) { t1 += sh1[i]; t2 += sh2[i]; }
    const float mu  = t1 * (1.f / DM);
    const float var = t2 * (1.f / DM) - mu * mu;
    const float rs  = rsqrtf(var + 1e-5f);
    float4 gv = ((const float4*)g)[t];
    float4 bv = ((const float4*)b)[t];
    __half2 h0 = __floats2half2_rn((v.x - mu) * rs * gv.x + bv.x,
                                   (v.y - mu) * rs * gv.y + bv.y);
    __half2 h1 = __floats2half2_rn((v.z - mu) * rs * gv.z + bv.z,
                                   (v.w - mu) * rs * gv.w + bv.w);
    uint2 o; o.x = *(uint32_t*)&h0; o.y = *(uint32_t*)&h1;
    ((uint2*)(out + (size_t)row * DM))[t] = o;
}

// ---------------- depthwise causal conv + SiLU ----------------
// 4 d-channels x 4 rows per thread; uint2 (4-half) vector loads
__global__ void conv_silu_kernel(const float* __restrict__ cw,
                                 const float* __restrict__ cb)
{
    const int gid = blockIdx.x * 256 + threadIdx.x;   // over (ROWS/4)*(DI/4)
    const int dq  = gid & (DI / 4 - 1);
    const int d0  = dq * 4;
    const int seg = gid >> 9;
    const int row0 = seg * 4;
    const int l0   = row0 & (LSEQ - 1);
    float w[4][4], bs[4];
    #pragma unroll
    for (int c = 0; c < 4; c++) {
        const float4 w4 = ((const float4*)cw)[d0 + c];
        w[c][0] = w4.x; w[c][1] = w4.y; w[c][2] = w4.z; w[c][3] = w4.w;
        bs[c] = cb[d0 + c];
    }
    const __half* base = g_xzh + (size_t)row0 * (2 * DI) + d0;
    float xv[7][4];
    #pragma unroll
    for (int j = 0; j < 7; j++) {
        const int ls = l0 - 3 + j;
        if (ls >= 0) {
            const uint2 u = *(const uint2*)(base + (ptrdiff_t)(j - 3) * (2 * DI));
            const __half2 p0 = *(const __half2*)&u.x;
            const __half2 p1 = *(const __half2*)&u.y;
            xv[j][0] = __low2float(p0);  xv[j][1] = __high2float(p0);
            xv[j][2] = __low2float(p1);  xv[j][3] = __high2float(p1);
        } else {
            xv[j][0] = xv[j][1] = xv[j][2] = xv[j][3] = 0.f;
        }
    }
    __half* outp = g_xph + (size_t)row0 * DI + d0;
    #pragma unroll
    for (int j = 0; j < 4; j++) {
        __half h[4];
        #pragma unroll
        for (int c = 0; c < 4; c++) {
            const float acc = bs[c] + w[c][0] * xv[j][c] + w[c][1] * xv[j+1][c]
                                    + w[c][2] * xv[j+2][c] + w[c][3] * xv[j+3][c];
            const float sig = 1.f / (1.f + expf(-acc));
            h[c] = __float2half_rn(acc * sig);
        }
        uint2 o;
        __half2 o0 = __halves2half2(h[0], h[1]);
        __half2 o1 = __halves2half2(h[2], h[3]);
        o.x = *(uint32_t*)&o0; o.y = *(uint32_t*)&o1;
        *(uint2*)(outp + (size_t)j * DI) = o;
    }
}

// ---------------- chunked SSM scan (2 d-channels per thread) ----------------
__global__ void scan_p1(const float* __restrict__ a_log)
{
    const int dp = blockIdx.x * 256 + threadIdx.x;   // 0..DI/2-1
    const int d  = dp * 2;
    const int c = blockIdx.y;
    const int b = blockIdx.z;
    const float Aa0 = -expf(a_log[2 * d + 0]);
    const float Aa1 = -expf(a_log[2 * d + 1]);
    const float Ab0 = -expf(a_log[2 * d + 2]);
    const float Ab1 = -expf(a_log[2 * d + 3]);
    const size_t l0 = (size_t)c * CL;
    const __half* dtp = g_dth  + ((size_t)b * LSEQ + l0) * DI + d;
    const __half* xpp = g_xph  + ((size_t)b * LSEQ + l0) * DI + d;
    const float*  bcp = g_xdbl + ((size_t)b * LSEQ + l0) * XPJ + DTR;
    float ha0 = 0.f, ha1 = 0.f, hb0 = 0.f, hb1 = 0.f, sda = 0.f, sdb = 0.f;
    for (int l = 0; l < CL; l++) {
        const __half2 dt2 = *(const __half2*)(dtp + (size_t)l * DI);
        const __half2 xp2 = *(const __half2*)(xpp + (size_t)l * DI);
        const float dta = __low2float(dt2), dtb = __high2float(dt2);
        const float xa  = __low2float(xp2), xb  = __high2float(xp2);
        const float B0 = bcp[(size_t)l * XPJ + 0];
        const float B1 = bcp[(size_t)l * XPJ + 1];
        const float dua = dta * xa, dub = dtb * xb;
        ha0 = fmaf(__expf(dta * Aa0), ha0, dua * B0);
        ha1 = fmaf(__expf(dta * Aa1), ha1, dua * B1);
        hb0 = fmaf(__expf(dtb * Ab0), hb0, dub * B0);
        hb1 = fmaf(__expf(dtb * Ab1), hb1, dub * B1);
        sda += dta; sdb += dtb;
    }
    const size_t idx = ((size_t)b * NCH + c) * DI + d;
    g_ch0[idx] = ha0;     g_ch1[idx] = ha1;     g_chS[idx] = sda;
    g_ch0[idx + 1] = hb0; g_ch1[idx + 1] = hb1; g_chS[idx + 1] = sdb;
}

__global__ void scan_p2(const float* __restrict__ a_log)
{
    const int d = blockIdx.x * 256 + threadIdx.x;
    const int b = blockIdx.y;
    const float A0 = -expf(a_log[2 * d + 0]);
    const float A1 = -expf(a_log[2 * d + 1]);
    float hs0 = 0.f, hs1 = 0.f;
    for (int c = 0; c < NCH; c++) {
        const size_t idx = ((size_t)b * NCH + c) * DI + d;
        g_hs0[idx] = hs0; g_hs1[idx] = hs1;
        const float s = g_chS[idx];
        hs0 = fmaf(__expf(A0 * s), hs0, g_ch0[idx]);
        hs1 = fmaf(__expf(A1 * s), hs1, g_ch1[idx]);
    }
}

__global__ void scan_p3(const float* __restrict__ a_log,
                        const float* __restrict__ d_skip)
{
    const int dp = blockIdx.x * 256 + threadIdx.x;   // 0..DI/2-1
    const int d  = dp * 2;
    const int c = blockIdx.y;
    const int b = blockIdx.z;
    const float Aa0 = -expf(a_log[2 * d + 0]);
    const float Aa1 = -expf(a_log[2 * d + 1]);
    const float Ab0 = -expf(a_log[2 * d + 2]);
    const float Ab1 = -expf(a_log[2 * d + 3]);
    const float dska = d_skip[d], dskb = d_skip[d + 1];
    const size_t l0 = (size_t)c * CL;
    const __half* dtp = g_dth  + ((size_t)b * LSEQ + l0) * DI + d;
    const __half* xpp = g_xph  + ((size_t)b * LSEQ + l0) * DI + d;
    const float*  bcp = g_xdbl + ((size_t)b * LSEQ + l0) * XPJ + DTR;
    const __half* zp  = g_xzh  + ((size_t)b * LSEQ + l0) * (2 * DI) + DI + d;
    __half* gp        = g_gateh + ((size_t)b * LSEQ + l0) * DI + d;
    const size_t idx = ((size_t)b * NCH + c) * DI + d;
    float ha0 = g_hs0[idx],     ha1 = g_hs1[idx];
    float hb0 = g_hs0[idx + 1], hb1 = g_hs1[idx + 1];
    for (int l = 0; l < CL; l++) {
        const __half2 dt2 = *(const __half2*)(dtp + (size_t)l * DI);
        const __half2 xp2 = *(const __half2*)(xpp + (size_t)l * DI);
        const __half2 z2  = *(const __half2*)(zp  + (size_t)l * (2 * DI));
        const float dta = __low2float(dt2), dtb = __high2float(dt2);
        const float xa  = __low2float(xp2), xb  = __high2float(xp2);
        const float za  = __low2float(z2),  zb  = __high2float(z2);
        const float B0 = bcp[(size_t)l * XPJ + 0];
        const float B1 = bcp[(size_t)l * XPJ + 1];
        const float C0 = bcp[(size_t)l * XPJ + 2];
        const float C1 = bcp[(size_t)l * XPJ + 3];
        const float dua = dta * xa, dub = dtb * xb;
        ha0 = fmaf(__expf(dta * Aa0), ha0, dua * B0);
        ha1 = fmaf(__expf(dta * Aa1), ha1, dua * B1);
        hb0 = fmaf(__expf(dtb * Ab0), hb0, dub * B0);
        hb1 = fmaf(__expf(dtb * Ab1), hb1, dub * B1);
        const float ya = ha0 * C0 + ha1 * C1;
        const float yb = hb0 * C0 + hb1 * C1;
        const float sa = za / (1.f + expf(-za));
        const float sb = zb / (1.f + expf(-zb));
        const __half2 o = __floats2half2_rn((ya + dska * xa) * sa,
                                            (yb + dskb * xb) * sb);
        *(__half2*)(gp + (size_t)l * DI) = o;
    }
}

// ---------------- launch ----------------
extern "C" void kernel_launch(void* const* d_in, const int* in_sizes, int n_in,
                              void* d_out, int out_size)
{
    const float* x       = (const float*)d_in[0];
    const float* w_in    = (const float*)d_in[1];
    const float* conv_w  = (const float*)d_in[2];
    const float* conv_b  = (const float*)d_in[3];
    const float* w_xproj = (const float*)d_in[4];
    const float* w_dt    = (const float*)d_in[5];
    const float* b_dt    = (const float*)d_in[6];
    const float* a_log   = (const float*)d_in[7];
    const float* d_skip  = (const float*)d_in[8];
    const float* w_out   = (const float*)d_in[9];
    const float* ln1_g   = (const float*)d_in[10];
    const float* ln1_b   = (const float*)d_in[11];
    const float* ln2_g   = (const float*)d_in[12];
    const float* ln2_b   = (const float*)d_in[13];
    const float* ffn_w1  = (const float*)d_in[14];
    const float* ffn_b1  = (const float*)d_in[15];
    const float* ffn_w2  = (const float*)d_in[16];
    const float* ffn_b2  = (const float*)d_in[17];
    float* out = (float*)d_out;

    float *p_xdbl, *p_h, *p_part0;
    __half *p_xzh, *p_dth, *p_ln1h, *p_xph, *p_xdblh, *p_gateh, *p_ln2h, *p_f1h;
    __half *p_w_inh, *p_w_xprjh, *p_w_dtwh, *p_w_outh, *p_ffn1h, *p_ffn2h;
    cudaGetSymbolAddress((void**)&p_xdbl,    g_xdbl);
    cudaGetSymbolAddress((void**)&p_h,       g_h);
    cudaGetSymbolAddress((void**)&p_part0,   g_part);
    cudaGetSymbolAddress((void**)&p_xzh,     g_xzh);
    cudaGetSymbolAddress((void**)&p_dth,     g_dth);
    cudaGetSymbolAddress((void**)&p_ln1h,    g_ln1h);
    cudaGetSymbolAddress((void**)&p_xph,     g_xph);
    cudaGetSymbolAddress((void**)&p_xdblh,   g_xdblh);
    cudaGetSymbolAddress((void**)&p_gateh,   g_gateh);
    cudaGetSymbolAddress((void**)&p_ln2h,    g_ln2h);
    cudaGetSymbolAddress((void**)&p_f1h,     g_f1h);
    cudaGetSymbolAddress((void**)&p_w_inh,   g_w_inh);
    cudaGetSymbolAddress((void**)&p_w_xprjh, g_w_xprjh);
    cudaGetSymbolAddress((void**)&p_w_dtwh,  g_w_dth);
    cudaGetSymbolAddress((void**)&p_w_outh,  g_w_outh);
    cudaGetSymbolAddress((void**)&p_ffn1h,   g_ffn1h);
    cudaGetSymbolAddress((void**)&p_ffn2h,   g_ffn2h);

    static bool attr_done = false;
    if (!attr_done) {
        cudaFuncSetAttribute(hgemm_kernel<EPI_NONE, true>,      cudaFuncAttributeMaxDynamicSharedMemorySize, HGEMM_SMEM);
        cudaFuncSetAttribute(hgemm_kernel<EPI_NONE, false>,     cudaFuncAttributeMaxDynamicSharedMemorySize, HGEMM_SMEM);
        cudaFuncSetAttribute(hgemm_kernel<EPI_SP_BIAS, true>,   cudaFuncAttributeMaxDynamicSharedMemorySize, HGEMM_SMEM);
        cudaFuncSetAttribute(hgemm_kernel<EPI_RELU_BIAS, true>, cudaFuncAttributeMaxDynamicSharedMemorySize, HGEMM_SMEM);
        cudaFuncSetAttribute(hgemm_kernel<EPI_RES, false>,      cudaFuncAttributeMaxDynamicSharedMemorySize, HGEMM_SMEM);
        cudaFuncSetAttribute(hgemm_kernel<EPI_BIAS_RES, false>, cudaFuncAttributeMaxDynamicSharedMemorySize, HGEMM_SMEM);
        attr_done = true;
    }

    const int MB = ROWS / 128;   // 64

    // 0) weights -> fp16
    {
        const int n0 = 2*DI*DM/4, n1 = XPJ*DI/4, n2 = DI*DTR/4,
                  n3 = DM*DI/4, n4 = DM*DM/4, n5 = DM*DM/4;
        const int tot = n0+n1+n2+n3+n4+n5;
        cvt_weights<<<(tot + 255) / 256, 256>>>(
            (const float4*)w_in, n0, (const float4*)w_xproj, n1,
            (const float4*)w_dt, n2, (const float4*)w_out, n3,
            (const float4*)ffn_w1, n4, (const float4*)ffn_w2, n5);
    }
    // 1) LN1 -> fp16
    ln_kernel<<<ROWS, 256>>>(x, ln1_g, ln1_b, p_ln1h);
    // 2) xz = ln1 @ w_in^T -> fp16
    hgemm_kernel<EPI_NONE, true><<<dim3((2 * DI) / 128, MB), 256, HGEMM_SMEM>>>(
        p_ln1h, DM, p_w_inh, DM, nullptr, nullptr, nullptr, p_xzh,
        2 * DI, DM, 2 * DI, (2 * DI) / 128, 0, 0);
    // 3) conv + SiLU -> xp fp16
    conv_silu_kernel<<<(ROWS / 4) * (DI / 4) / 256, 256>>>(conv_w, conv_b);
    // 4) x_dbl: split-K x4 over K=2048, single launch -> fp32 partials
    hgemm_kernel<EPI_NONE, false><<<dim3(4, MB), 256, HGEMM_SMEM>>>(
        p_xph, DI, p_w_xprjh, DI, nullptr, nullptr, p_part0, nullptr,
        XPJ, 512, XPJ, 1, 512, (size_t)ROWS * XPJ);
    xproj_reduce<<<(ROWS * XPJ + 255) / 256, 256>>>();
    // 5) dt = softplus(x_dbl[:, :64] @ w_dt^T + b_dt) -> fp16
    hgemm_kernel<EPI_SP_BIAS, true><<<dim3(DI / 128, MB), 256, HGEMM_SMEM>>>(
        p_xdblh, DTR, p_w_dtwh, DTR, b_dt, nullptr, nullptr, p_dth,
        DI, DTR, DI, DI / 128, 0, 0);
    // 6) chunked scan + fused gate -> fp16
    scan_p1<<<dim3(DI / 512, NCH, BATCH), 256>>>(a_log);
    scan_p2<<<dim3(DI / 256, BATCH), 256>>>(a_log);
    scan_p3<<<dim3(DI / 512, NCH, BATCH), 256>>>(a_log, d_skip);
    // 7) h = x + gate @ w_out^T -> fp32
    hgemm_kernel<EPI_RES, false><<<dim3(DM / 128, MB), 256, HGEMM_SMEM>>>(
        p_gateh, DI, p_w_outh, DI, nullptr, x, p_h, nullptr,
        DM, DI, DM, DM / 128, 0, 0);
    // 8) LN2 -> fp16
    ln_kernel<<<ROWS, 256>>>(p_h, ln2_g, ln2_b, p_ln2h);
    // 9) f1 = relu(ln2 @ ffn_w1^T + b1) -> fp16
    hgemm_kernel<EPI_RELU_BIAS, true><<<dim3(DM / 128, MB), 256, HGEMM_SMEM>>>(
        p_ln2h, DM, p_ffn1h, DM, ffn_b1, nullptr, nullptr, p_f1h,
        DM, DM, DM, DM / 128, 0, 0);
    // 10) out = h + f1 @ ffn_w2^T + b2 -> fp32
    hgemm_kernel<EPI_BIAS_RES, false><<<dim3(DM / 128, MB), 256, HGEMM_SMEM>>>(
        p_f1h, DM, p_ffn2h, DM, ffn_b2, p_h, out, nullptr,
        DM, DM, DM, DM / 128, 0, 0);
}

// round 17
// speedup vs baseline: 1.1166x; 1.1166x over previous
#include <cuda_runtime.h>
#include <cuda_fp16.h>
#include <math.h>
#include <stdint.h>

// ---------------- problem constants ----------------
#define DM    1024
#define DI    2048
#define LSEQ  4096
#define BATCH 2
#define ROWS  (BATCH*LSEQ)    // 8192
#define XPJ   68
#define DTR   64
#define NCH   64
#define CL    (LSEQ/NCH)      // 64

// ---------------- fp32 scratch ----------------
__device__ float g_xdbl[(size_t)ROWS*XPJ];
__device__ float g_h   [(size_t)ROWS*DM];
__device__ float g_part[4][(size_t)ROWS*XPJ];
// chunked-scan state
__device__ float g_ch0[BATCH*NCH*DI];
__device__ float g_ch1[BATCH*NCH*DI];
__device__ float g_chS[BATCH*NCH*DI];
__device__ float g_hs0[BATCH*NCH*DI];
__device__ float g_hs1[BATCH*NCH*DI];
// ---------------- fp16 scratch ----------------
__device__ __half g_xzh  [(size_t)ROWS*2*DI];
__device__ __half g_dth  [(size_t)ROWS*DI];
__device__ __half g_ln1h [(size_t)ROWS*DM];
__device__ __half g_xph  [(size_t)ROWS*DI];
__device__ __half g_xdblh[(size_t)ROWS*DTR];
__device__ __half g_gateh[(size_t)ROWS*DI];
__device__ __half g_ln2h [(size_t)ROWS*DM];
__device__ __half g_f1h  [(size_t)ROWS*DM];
// fp16 weights
__device__ __half g_w_inh  [(size_t)2*DI*DM];
__device__ __half g_w_xprjh[(size_t)XPJ*DI];
__device__ __half g_w_dth  [(size_t)DI*DTR];
__device__ __half g_w_outh [(size_t)DM*DI];
__device__ __half g_ffn1h  [(size_t)DM*DM];
__device__ __half g_ffn2h  [(size_t)DM*DM];

// ==================== helpers ====================
__device__ __forceinline__ uint32_t smem_u32(const void* p) {
    uint32_t a;
    asm("{ .reg .u64 t; cvta.to.shared.u64 t, %1; cvt.u32.u64 %0, t; }" : "=r"(a) : "l"(p));
    return a;
}
__device__ __forceinline__ void cp16(uint32_t sm, const void* g) {
    asm volatile("cp.async.cg.shared.global [%0], [%1], 16;" :: "r"(sm), "l"(g));
}
__device__ __forceinline__ void cp16z(uint32_t sm, const void* g, uint32_t valid) {
    uint32_t sz = valid ? 16u : 0u;
    asm volatile("cp.async.cg.shared.global [%0], [%1], 16, %2;" :: "r"(sm), "l"(g), "r"(sz));
}
#define CP_COMMIT() asm volatile("cp.async.commit_group;" ::: "memory")
#define CP_WAIT2()  asm volatile("cp.async.wait_group 2;" ::: "memory")

__device__ __forceinline__ void mma16(float* c, const uint32_t* a, const uint32_t* b) {
    asm volatile("mma.sync.aligned.m16n8k16.row.col.f32.f16.f16.f32 "
                 "{%0,%1,%2,%3}, {%4,%5,%6,%7}, {%8,%9}, {%0,%1,%2,%3};"
                 : "+f"(c[0]), "+f"(c[1]), "+f"(c[2]), "+f"(c[3])
                 : "r"(a[0]), "r"(a[1]), "r"(a[2]), "r"(a[3]),
                   "r"(b[0]), "r"(b[1]));
}
#define LDSM4(r0, r1, r2, r3, addr) \
    asm volatile("ldmatrix.sync.aligned.m8n8.x4.shared.b16 {%0,%1,%2,%3}, [%4];" \
                 : "=r"(r0), "=r"(r1), "=r"(r2), "=r"(r3) : "r"(addr))

// ==================== fp16 mma.sync GEMM ====================
enum { EPI_NONE = 0, EPI_SP_BIAS = 1, EPI_RELU_BIAS = 2, EPI_RES = 3, EPI_BIAS_RES = 4 };

#define KTILE       64
#define TILE_BYTES  16384
#define STAGE_BYTES (2 * TILE_BYTES)
#define HGEMM_SMEM  (3 * STAGE_BYTES)         // 98304 -> 2 CTAs/SM

template<int EPI, bool HOUT>
__global__ __launch_bounds__(256, 2)
void hgemm_kernel(const __half* __restrict__ A, int lda,
                  const __half* __restrict__ W, int ldw,
                  const float* __restrict__ bias,
                  const float* __restrict__ res,
                  float* __restrict__ Cf,
                  __half* __restrict__ Ch,
                  int N, int K, int ldc,
                  int nbx, int kStride, size_t outStride)
{
    extern __shared__ char smraw[];
    const uint32_t sb = smem_u32(smraw);
    const int tid  = threadIdx.x;
    const int wid  = tid >> 5;
    const int lane = tid & 31;
    const int grp  = lane >> 2;
    const int thr  = lane & 3;
    const int bx   = blockIdx.x;
    const int sp   = bx / nbx;
    const int m0 = blockIdx.y * 128;
    const int n0 = (bx % nbx) * 128;
    A  += (size_t)sp * kStride;
    W  += (size_t)sp * kStride;
    Cf += (size_t)sp * outStride;
    const int KT = K / KTILE;
    const int wM = (wid & 3) * 32;
    const int wN = (wid >> 2) * 64;

    auto load_tile = [&](int kt) {
        const uint32_t st = sb + (kt % 3) * STAGE_BYTES;
        const int k0 = kt * KTILE;
        #pragma unroll
        for (int i = 0; i < 4; i++) {
            const int idx = tid + 256 * i;
            const int row = idx >> 3;
            const int c   = idx & 7;
            const uint32_t soff = (uint32_t)(row * 128 + ((c ^ (row & 7)) << 4));
            cp16(st + soff, A + (size_t)(m0 + row) * lda + k0 + c * 8);
            const int nr = n0 + row;
            const uint32_t valid = (nr < N);
            cp16z(st + TILE_BYTES + soff,
                  W + (size_t)(valid ? nr : 0) * ldw + k0 + c * 8, valid);
        }
    };

    float acc[2][8][4];
    #pragma unroll
    for (int mt = 0; mt < 2; mt++)
        #pragma unroll
        for (int nt = 0; nt < 8; nt++)
            #pragma unroll
            for (int q = 0; q < 4; q++) acc[mt][nt][q] = 0.f;

    uint32_t aOff[2]; int a7[2];
    #pragma unroll
    for (int mt = 0; mt < 2; mt++) {
        const int r = wM + mt * 16 + ((lane >> 3) & 1) * 8 + (lane & 7);
        aOff[mt] = (uint32_t)(r * 128); a7[mt] = r & 7;
    }
    const int aHi = lane >> 4;
    uint32_t bOff[4]; int b7[4];
    #pragma unroll
    for (int j = 0; j < 4; j++) {
        const int r = wN + j * 16 + (lane >> 4) * 8 + (lane & 7);
        bOff[j] = (uint32_t)(r * 128); b7[j] = r & 7;
    }
    const int bHi = (lane >> 3) & 1;

    load_tile(0); CP_COMMIT();
    if (KT > 1) load_tile(1);
    CP_COMMIT();

    for (int kt = 0; kt < KT; kt++) {
        if (kt + 2 < KT) load_tile(kt + 2);
        CP_COMMIT();
        CP_WAIT2();
        __syncthreads();

        const uint32_t Ab = sb + (kt % 3) * STAGE_BYTES;
        const uint32_t Bb = Ab + TILE_BYTES;
        #pragma unroll
        for (int ks = 0; ks < 4; ks++) {
            uint32_t af[2][4];
            #pragma unroll
            for (int mt = 0; mt < 2; mt++) {
                const uint32_t ad = Ab + aOff[mt]
                    + (uint32_t)((((ks << 1) + aHi) ^ a7[mt]) << 4);
                LDSM4(af[mt][0], af[mt][1], af[mt][2], af[mt][3], ad);
            }
            uint32_t bf[8][2];
            #pragma unroll
            for (int j = 0; j < 4; j++) {
                const uint32_t bd = Bb + bOff[j]
                    + (uint32_t)((((ks << 1) + bHi) ^ b7[j]) << 4);
                uint32_t r0, r1, r2, r3;
                LDSM4(r0, r1, r2, r3, bd);
                bf[2*j][0] = r0; bf[2*j][1] = r1;
                bf[2*j+1][0] = r2; bf[2*j+1][1] = r3;
            }
            #pragma unroll
            for (int mt = 0; mt < 2; mt++)
                #pragma unroll
                for (int nt = 0; nt < 8; nt++)
                    mma16(acc[mt][nt], af[mt], bf[nt]);
        }
        __syncthreads();
    }

    // epilogue
    #pragma unroll
    for (int mt = 0; mt < 2; mt++) {
        const int mA = m0 + wM + mt * 16 + grp;
        #pragma unroll
        for (int nt = 0; nt < 8; nt++) {
            const int col = n0 + wN + nt * 8 + 2 * thr;
            if (col >= N) continue;
            float v0 = acc[mt][nt][0], v1 = acc[mt][nt][1];
            float v2 = acc[mt][nt][2], v3 = acc[mt][nt][3];
            if (EPI == EPI_SP_BIAS) {
                const float b0 = bias[col], b1 = bias[col + 1];
                v0 += b0; v1 += b1; v2 += b0; v3 += b1;
                v0 = (v0 > 20.f) ? v0 : log1pf(expf(v0));
                v1 = (v1 > 20.f) ? v1 : log1pf(expf(v1));
                v2 = (v2 > 20.f) ? v2 : log1pf(expf(v2));
                v3 = (v3 > 20.f) ? v3 : log1pf(expf(v3));
            } else if (EPI == EPI_RELU_BIAS) {
                const float b0 = bias[col], b1 = bias[col + 1];
                v0 = fmaxf(v0 + b0, 0.f); v1 = fmaxf(v1 + b1, 0.f);
                v2 = fmaxf(v2 + b0, 0.f); v3 = fmaxf(v3 + b1, 0.f);
            } else if (EPI == EPI_RES) {
                const float2 r0 = *(const float2*)(res + (size_t)mA * ldc + col);
                const float2 r1 = *(const float2*)(res + (size_t)(mA + 8) * ldc + col);
                v0 += r0.x; v1 += r0.y; v2 += r1.x; v3 += r1.y;
            } else if (EPI == EPI_BIAS_RES) {
                const float b0 = bias[col], b1 = bias[col + 1];
                const float2 r0 = *(const float2*)(res + (size_t)mA * ldc + col);
                const float2 r1 = *(const float2*)(res + (size_t)(mA + 8) * ldc + col);
                v0 += b0 + r0.x; v1 += b1 + r0.y; v2 += b0 + r1.x; v3 += b1 + r1.y;
            }
            if (HOUT) {
                *(__half2*)(Ch + (size_t)mA * ldc + col)       = __floats2half2_rn(v0, v1);
                *(__half2*)(Ch + (size_t)(mA + 8) * ldc + col) = __floats2half2_rn(v2, v3);
            } else {
                *(float2*)(Cf + (size_t)mA * ldc + col)       = make_float2(v0, v1);
                *(float2*)(Cf + (size_t)(mA + 8) * ldc + col) = make_float2(v2, v3);
            }
        }
    }
}

// ---------------- weight fp32 -> fp16 ----------------
__global__ void cvt_weights(const float4* s0, int n0, const float4* s1, int n1,
                            const float4* s2, int n2, const float4* s3, int n3,
                            const float4* s4, int n4, const float4* s5, int n5)
{
    int i = blockIdx.x * 256 + threadIdx.x;
    const float4* s; __half2* d;
    __half2* d0 = (__half2*)g_w_inh;  __half2* d1 = (__half2*)g_w_xprjh;
    __half2* d2 = (__half2*)g_w_dth;  __half2* d3 = (__half2*)g_w_outh;
    __half2* d4 = (__half2*)g_ffn1h;  __half2* d5 = (__half2*)g_ffn2h;
    if      (i < n0) { s = s0; d = d0; }
    else if ((i -= n0) < n1) { s = s1; d = d1; }
    else if ((i -= n1) < n2) { s = s2; d = d2; }
    else if ((i -= n2) < n3) { s = s3; d = d3; }
    else if ((i -= n3) < n4) { s = s4; d = d4; }
    else if ((i -= n4) < n5) { s = s5; d = d5; }
    else return;
    const float4 v = s[i];
    d[2*i]   = __floats2half2_rn(v.x, v.y);
    d[2*i+1] = __floats2half2_rn(v.z, v.w);
}

// ---------------- split-K reduce for x-proj ----------------
__global__ void xproj_reduce()
{
    const int i = blockIdx.x * 256 + threadIdx.x;
    if (i >= ROWS * XPJ) return;
    const float v = g_part[0][i] + g_part[1][i] + g_part[2][i] + g_part[3][i];
    g_xdbl[i] = v;
    const int m = i / XPJ, j = i - m * XPJ;
    if (j < DTR) g_xdblh[(size_t)m * DTR + j] = __float2half_rn(v);
}

// ---------------- LayerNorm -> fp16 out ----------------
__global__ void ln_kernel(const float* __restrict__ in,
                          const float* __restrict__ g,
                          const float* __restrict__ b,
                          __half* __restrict__ out)
{
    const int row = blockIdx.x;
    const int t = threadIdx.x;
    const float4* p = (const float4*)(in + (size_t)row * DM);
    float4 v = p[t];
    float s1 = v.x + v.y + v.z + v.w;
    float s2 = v.x*v.x + v.y*v.y + v.z*v.z + v.w*v.w;
    #pragma unroll
    for (int o = 16; o > 0; o >>= 1) {
        s1 += __shfl_xor_sync(0xFFFFFFFFu, s1, o);
        s2 += __shfl_xor_sync(0xFFFFFFFFu, s2, o);
    }
    __shared__ float sh1[8], sh2[8];
    if ((t & 31) == 0) { sh1[t >> 5] = s1; sh2[t >> 5] = s2; }
    __syncthreads();
    float t1 = 0.f, t2 = 0.f;
    #pragma unroll
    for (int i = 0; i < 8; i++) { t1 += sh1[i]; t2 += sh2[i]; }
    const float mu  = t1 * (1.f / DM);
    const float var = t2 * (1.f / DM) - mu * mu;
    const float rs  = rsqrtf(var + 1e-5f);
    float4 gv = ((const float4*)g)[t];
    float4 bv = ((const float4*)b)[t];
    __half2 h0 = __floats2half2_rn((v.x - mu) * rs * gv.x + bv.x,
                                   (v.y - mu) * rs * gv.y + bv.y);
    __half2 h1 = __floats2half2_rn((v.z - mu) * rs * gv.z + bv.z,
                                   (v.w - mu) * rs * gv.w + bv.w);
    uint2 o; o.x = *(uint32_t*)&h0; o.y = *(uint32_t*)&h1;
    ((uint2*)(out + (size_t)row * DM))[t] = o;
}

// ---------------- depthwise causal conv + SiLU ----------------
// 4 d-channels x 4 rows per thread; uint2 (4-half) vector loads
__global__ void conv_silu_kernel(const float* __restrict__ cw,
                                 const float* __restrict__ cb)
{
    const int gid = blockIdx.x * 256 + threadIdx.x;   // over (ROWS/4)*(DI/4)
    const int dq  = gid & (DI / 4 - 1);
    const int d0  = dq * 4;
    const int seg = gid >> 9;
    const int row0 = seg * 4;
    const int l0   = row0 & (LSEQ - 1);
    float w[4][4], bs[4];
    #pragma unroll
    for (int c = 0; c < 4; c++) {
        const float4 w4 = ((const float4*)cw)[d0 + c];
        w[c][0] = w4.x; w[c][1] = w4.y; w[c][2] = w4.z; w[c][3] = w4.w;
        bs[c] = cb[d0 + c];
    }
    const __half* base = g_xzh + (size_t)row0 * (2 * DI) + d0;
    float xv[7][4];
    #pragma unroll
    for (int j = 0; j < 7; j++) {
        const int ls = l0 - 3 + j;
        if (ls >= 0) {
            const uint2 u = *(const uint2*)(base + (ptrdiff_t)(j - 3) * (2 * DI));
            const __half2 p0 = *(const __half2*)&u.x;
            const __half2 p1 = *(const __half2*)&u.y;
            xv[j][0] = __low2float(p0);  xv[j][1] = __high2float(p0);
            xv[j][2] = __low2float(p1);  xv[j][3] = __high2float(p1);
        } else {
            xv[j][0] = xv[j][1] = xv[j][2] = xv[j][3] = 0.f;
        }
    }
    __half* outp = g_xph + (size_t)row0 * DI + d0;
    #pragma unroll
    for (int j = 0; j < 4; j++) {
        __half h[4];
        #pragma unroll
        for (int c = 0; c < 4; c++) {
            const float acc = bs[c] + w[c][0] * xv[j][c] + w[c][1] * xv[j+1][c]
                                    + w[c][2] * xv[j+2][c] + w[c][3] * xv[j+3][c];
            const float sig = 1.f / (1.f + expf(-acc));
            h[c] = __float2half_rn(acc * sig);
        }
        uint2 o;
        __half2 o0 = __halves2half2(h[0], h[1]);
        __half2 o1 = __halves2half2(h[2], h[3]);
        o.x = *(uint32_t*)&o0; o.y = *(uint32_t*)&o1;
        *(uint2*)(outp + (size_t)j * DI) = o;
    }
}

// ---------------- chunked SSM scan (scalar, 1 d-channel per thread) ----------------
__global__ void scan_p1(const float* __restrict__ a_log)
{
    const int d = blockIdx.x * 256 + threadIdx.x;
    const int c = blockIdx.y;
    const int b = blockIdx.z;
    const float A0 = -expf(a_log[2 * d + 0]);
    const float A1 = -expf(a_log[2 * d + 1]);
    const size_t l0 = (size_t)c * CL;
    const __half* dtp = g_dth  + ((size_t)b * LSEQ + l0) * DI + d;
    const __half* xpp = g_xph  + ((size_t)b * LSEQ + l0) * DI + d;
    const float*  bcp = g_xdbl + ((size_t)b * LSEQ + l0) * XPJ + DTR;
    float h0 = 0.f, h1 = 0.f, sdt = 0.f;
    for (int l = 0; l < CL; l++) {
        const float dtv = __half2float(dtp[(size_t)l * DI]);
        const float xv  = __half2float(xpp[(size_t)l * DI]);
        const float B0 = bcp[(size_t)l * XPJ + 0];
        const float B1 = bcp[(size_t)l * XPJ + 1];
        const float du = dtv * xv;
        h0 = fmaf(__expf(dtv * A0), h0, du * B0);
        h1 = fmaf(__expf(dtv * A1), h1, du * B1);
        sdt += dtv;
    }
    const size_t idx = ((size_t)b * NCH + c) * DI + d;
    g_ch0[idx] = h0; g_ch1[idx] = h1; g_chS[idx] = sdt;
}

__global__ void scan_p2(const float* __restrict__ a_log)
{
    const int d = blockIdx.x * 256 + threadIdx.x;
    const int b = blockIdx.y;
    const float A0 = -expf(a_log[2 * d + 0]);
    const float A1 = -expf(a_log[2 * d + 1]);
    float hs0 = 0.f, hs1 = 0.f;
    for (int c = 0; c < NCH; c++) {
        const size_t idx = ((size_t)b * NCH + c) * DI + d;
        g_hs0[idx] = hs0; g_hs1[idx] = hs1;
        const float s = g_chS[idx];
        hs0 = fmaf(__expf(A0 * s), hs0, g_ch0[idx]);
        hs1 = fmaf(__expf(A1 * s), hs1, g_ch1[idx]);
    }
}

__global__ void scan_p3(const float* __restrict__ a_log,
                        const float* __restrict__ d_skip)
{
    const int d = blockIdx.x * 256 + threadIdx.x;
    const int c = blockIdx.y;
    const int b = blockIdx.z;
    const float A0 = -expf(a_log[2 * d + 0]);
    const float A1 = -expf(a_log[2 * d + 1]);
    const float dsk = d_skip[d];
    const size_t l0 = (size_t)c * CL;
    const __half* dtp = g_dth  + ((size_t)b * LSEQ + l0) * DI + d;
    const __half* xpp = g_xph  + ((size_t)b * LSEQ + l0) * DI + d;
    const float*  bcp = g_xdbl + ((size_t)b * LSEQ + l0) * XPJ + DTR;
    const __half* zp  = g_xzh  + ((size_t)b * LSEQ + l0) * (2 * DI) + DI + d;
    __half* gp        = g_gateh + ((size_t)b * LSEQ + l0) * DI + d;
    const size_t idx = ((size_t)b * NCH + c) * DI + d;
    float h0 = g_hs0[idx], h1 = g_hs1[idx];
    for (int l = 0; l < CL; l++) {
        const float dtv = __half2float(dtp[(size_t)l * DI]);
        const float xv  = __half2float(xpp[(size_t)l * DI]);
        const float B0 = bcp[(size_t)l * XPJ + 0];
        const float B1 = bcp[(size_t)l * XPJ + 1];
        const float C0 = bcp[(size_t)l * XPJ + 2];
        const float C1 = bcp[(size_t)l * XPJ + 3];
        const float z  = __half2float(zp[(size_t)l * (2 * DI)]);
        const float du = dtv * xv;
        h0 = fmaf(__expf(dtv * A0), h0, du * B0);
        h1 = fmaf(__expf(dtv * A1), h1, du * B1);
        const float y = h0 * C0 + h1 * C1;
        const float sig = 1.f / (1.f + expf(-z));
        gp[(size_t)l * DI] = __float2half_rn((y + dsk * xv) * z * sig);
    }
}

// ---------------- launch ----------------
extern "C" void kernel_launch(void* const* d_in, const int* in_sizes, int n_in,
                              void* d_out, int out_size)
{
    const float* x       = (const float*)d_in[0];
    const float* w_in    = (const float*)d_in[1];
    const float* conv_w  = (const float*)d_in[2];
    const float* conv_b  = (const float*)d_in[3];
    const float* w_xproj = (const float*)d_in[4];
    const float* w_dt    = (const float*)d_in[5];
    const float* b_dt    = (const float*)d_in[6];
    const float* a_log   = (const float*)d_in[7];
    const float* d_skip  = (const float*)d_in[8];
    const float* w_out   = (const float*)d_in[9];
    const float* ln1_g   = (const float*)d_in[10];
    const float* ln1_b   = (const float*)d_in[11];
    const float* ln2_g   = (const float*)d_in[12];
    const float* ln2_b   = (const float*)d_in[13];
    const float* ffn_w1  = (const float*)d_in[14];
    const float* ffn_b1  = (const float*)d_in[15];
    const float* ffn_w2  = (const float*)d_in[16];
    const float* ffn_b2  = (const float*)d_in[17];
    float* out = (float*)d_out;

    float *p_xdbl, *p_h, *p_part0;
    __half *p_xzh, *p_dth, *p_ln1h, *p_xph, *p_xdblh, *p_gateh, *p_ln2h, *p_f1h;
    __half *p_w_inh, *p_w_xprjh, *p_w_dtwh, *p_w_outh, *p_ffn1h, *p_ffn2h;
    cudaGetSymbolAddress((void**)&p_xdbl,    g_xdbl);
    cudaGetSymbolAddress((void**)&p_h,       g_h);
    cudaGetSymbolAddress((void**)&p_part0,   g_part);
    cudaGetSymbolAddress((void**)&p_xzh,     g_xzh);
    cudaGetSymbolAddress((void**)&p_dth,     g_dth);
    cudaGetSymbolAddress((void**)&p_ln1h,    g_ln1h);
    cudaGetSymbolAddress((void**)&p_xph,     g_xph);
    cudaGetSymbolAddress((void**)&p_xdblh,   g_xdblh);
    cudaGetSymbolAddress((void**)&p_gateh,   g_gateh);
    cudaGetSymbolAddress((void**)&p_ln2h,    g_ln2h);
    cudaGetSymbolAddress((void**)&p_f1h,     g_f1h);
    cudaGetSymbolAddress((void**)&p_w_inh,   g_w_inh);
    cudaGetSymbolAddress((void**)&p_w_xprjh, g_w_xprjh);
    cudaGetSymbolAddress((void**)&p_w_dtwh,  g_w_dth);
    cudaGetSymbolAddress((void**)&p_w_outh,  g_w_outh);
    cudaGetSymbolAddress((void**)&p_ffn1h,   g_ffn1h);
    cudaGetSymbolAddress((void**)&p_ffn2h,   g_ffn2h);

    static bool attr_done = false;
    if (!attr_done) {
        cudaFuncSetAttribute(hgemm_kernel<EPI_NONE, true>,      cudaFuncAttributeMaxDynamicSharedMemorySize, HGEMM_SMEM);
        cudaFuncSetAttribute(hgemm_kernel<EPI_NONE, false>,     cudaFuncAttributeMaxDynamicSharedMemorySize, HGEMM_SMEM);
        cudaFuncSetAttribute(hgemm_kernel<EPI_SP_BIAS, true>,   cudaFuncAttributeMaxDynamicSharedMemorySize, HGEMM_SMEM);
        cudaFuncSetAttribute(hgemm_kernel<EPI_RELU_BIAS, true>, cudaFuncAttributeMaxDynamicSharedMemorySize, HGEMM_SMEM);
        cudaFuncSetAttribute(hgemm_kernel<EPI_RES, false>,      cudaFuncAttributeMaxDynamicSharedMemorySize, HGEMM_SMEM);
        cudaFuncSetAttribute(hgemm_kernel<EPI_BIAS_RES, false>, cudaFuncAttributeMaxDynamicSharedMemorySize, HGEMM_SMEM);
        attr_done = true;
    }

    const int MB = ROWS / 128;   // 64

    // 0) weights -> fp16
    {
        const int n0 = 2*DI*DM/4, n1 = XPJ*DI/4, n2 = DI*DTR/4,
                  n3 = DM*DI/4, n4 = DM*DM/4, n5 = DM*DM/4;
        const int tot = n0+n1+n2+n3+n4+n5;
        cvt_weights<<<(tot + 255) / 256, 256>>>(
            (const float4*)w_in, n0, (const float4*)w_xproj, n1,
            (const float4*)w_dt, n2, (const float4*)w_out, n3,
            (const float4*)ffn_w1, n4, (const float4*)ffn_w2, n5);
    }
    // 1) LN1 -> fp16
    ln_kernel<<<ROWS, 256>>>(x, ln1_g, ln1_b, p_ln1h);
    // 2) xz = ln1 @ w_in^T -> fp16
    hgemm_kernel<EPI_NONE, true><<<dim3((2 * DI) / 128, MB), 256, HGEMM_SMEM>>>(
        p_ln1h, DM, p_w_inh, DM, nullptr, nullptr, nullptr, p_xzh,
        2 * DI, DM, 2 * DI, (2 * DI) / 128, 0, 0);
    // 3) conv + SiLU -> xp fp16
    conv_silu_kernel<<<(ROWS / 4) * (DI / 4) / 256, 256>>>(conv_w, conv_b);
    // 4) x_dbl: split-K x4 over K=2048, single launch -> fp32 partials
    hgemm_kernel<EPI_NONE, false><<<dim3(4, MB), 256, HGEMM_SMEM>>>(
        p_xph, DI, p_w_xprjh, DI, nullptr, nullptr, p_part0, nullptr,
        XPJ, 512, XPJ, 1, 512, (size_t)ROWS * XPJ);
    xproj_reduce<<<(ROWS * XPJ + 255) / 256, 256>>>();
    // 5) dt = softplus(x_dbl[:, :64] @ w_dt^T + b_dt) -> fp16
    hgemm_kernel<EPI_SP_BIAS, true><<<dim3(DI / 128, MB), 256, HGEMM_SMEM>>>(
        p_xdblh, DTR, p_w_dtwh, DTR, b_dt, nullptr, nullptr, p_dth,
        DI, DTR, DI, DI / 128, 0, 0);
    // 6) chunked scan + fused gate -> fp16
    scan_p1<<<dim3(DI / 256, NCH, BATCH), 256>>>(a_log);
    scan_p2<<<dim3(DI / 256, BATCH), 256>>>(a_log);
    scan_p3<<<dim3(DI / 256, NCH, BATCH), 256>>>(a_log, d_skip);
    // 7) h = x + gate @ w_out^T -> fp32
    hgemm_kernel<EPI_RES, false><<<dim3(DM / 128, MB), 256, HGEMM_SMEM>>>(
        p_gateh, DI, p_w_outh, DI, nullptr, x, p_h, nullptr,
        DM, DI, DM, DM / 128, 0, 0);
    // 8) LN2 -> fp16
    ln_kernel<<<ROWS, 256>>>(p_h, ln2_g, ln2_b, p_ln2h);
    // 9) f1 = relu(ln2 @ ffn_w1^T + b1) -> fp16
    hgemm_kernel<EPI_RELU_BIAS, true><<<dim3(DM / 128, MB), 256, HGEMM_SMEM>>>(
        p_ln2h, DM, p_ffn1h, DM, ffn_b1, nullptr, nullptr, p_f1h,
        DM, DM, DM, DM / 128, 0, 0);
    // 10) out = h + f1 @ ffn_w2^T + b2 -> fp32
    hgemm_kernel<EPI_BIAS_RES, false><<<dim3(DM / 128, MB), 256, HGEMM_SMEM>>>(
        p_f1h, DM, p_ffn2h, DM, ffn_b2, p_h, out, nullptr,
        DM, DM, DM, DM / 128, 0, 0);
}